// round 1
// baseline (speedup 1.0000x reference)
#include <cuda_runtime.h>
#include <math.h>

// Problem constants (fixed shapes from reference setup_inputs)
static constexpr int BATCH = 4;
static constexpr int C     = 512;
static constexpr int HW    = 4096;   // 64*64
static constexpr int G     = 32;     // groups
static constexpr int CPG   = C / G;  // 16 channels per group
static constexpr size_t CBS = (size_t)C * HW;   // per-batch stride of [c,hw] tensors
static constexpr size_t SBS = (size_t)HW * HW;  // per-batch stride of attention matrix

// -------- scratch (static __device__ globals; no allocation) --------
__device__ float g_hn[BATCH * C * HW];       // 32 MB
__device__ float g_q [BATCH * C * HW];
__device__ float g_k [BATCH * C * HW];
__device__ float g_v [BATCH * C * HW];
__device__ float g_s [(size_t)BATCH * HW * HW]; // 256 MB
__device__ float g_ao[BATCH * C * HW];

// =====================================================================
// GroupNorm: one block per (batch, group). Group data is a contiguous
// chunk of CPG*HW = 65536 floats. Two passes (reduce, then normalize).
// =====================================================================
__global__ void groupnorm_kernel(const float* __restrict__ x,
                                 const float* __restrict__ scale,
                                 const float* __restrict__ bias,
                                 float* __restrict__ out)
{
    const int bg = blockIdx.x;            // 0 .. BATCH*G-1
    const int b = bg / G, g = bg % G;
    const int N = CPG * HW;               // 65536
    const size_t base = ((size_t)b * C + (size_t)g * CPG) * HW;
    const float* xp = x + base;

    float s = 0.f, ss = 0.f;
    for (int i = threadIdx.x; i < N; i += blockDim.x) {
        float v = xp[i];
        s += v; ss += v * v;
    }
    __shared__ float sh_s[256], sh_q[256];
    sh_s[threadIdx.x] = s;
    sh_q[threadIdx.x] = ss;
    __syncthreads();
    for (int o = 128; o > 0; o >>= 1) {
        if (threadIdx.x < o) {
            sh_s[threadIdx.x] += sh_s[threadIdx.x + o];
            sh_q[threadIdx.x] += sh_q[threadIdx.x + o];
        }
        __syncthreads();
    }
    const float mean = sh_s[0] * (1.0f / N);
    const float var  = sh_q[0] * (1.0f / N) - mean * mean;
    const float inv  = rsqrtf(var + 1e-6f);

    for (int i = threadIdx.x; i < N; i += blockDim.x) {
        int ch = g * CPG + (i >> 12);     // i / HW
        out[base + i] = (xp[i] - mean) * inv * scale[ch] + bias[ch];
    }
}

// =====================================================================
// Row softmax over last axis: one block per row (4096 elems), row kept
// entirely in registers (16 per thread) -> single read + single write.
// =====================================================================
__global__ void softmax_kernel(float* __restrict__ sbuf)
{
    const size_t row = blockIdx.x;        // b*HW + i
    float* p = sbuf + row * (size_t)HW;
    const int t = threadIdx.x;

    float r[16];
    float m = -1e30f;
#pragma unroll
    for (int j = 0; j < 16; j++) {
        r[j] = p[t + j * 256];
        m = fmaxf(m, r[j]);
    }
    __shared__ float shm[8], shs[8];
#pragma unroll
    for (int o = 16; o > 0; o >>= 1) m = fmaxf(m, __shfl_xor_sync(0xffffffffu, m, o));
    if ((t & 31) == 0) shm[t >> 5] = m;
    __syncthreads();
    m = shm[0];
#pragma unroll
    for (int w = 1; w < 8; w++) m = fmaxf(m, shm[w]);

    float sum = 0.f;
#pragma unroll
    for (int j = 0; j < 16; j++) {
        r[j] = __expf(r[j] - m);
        sum += r[j];
    }
#pragma unroll
    for (int o = 16; o > 0; o >>= 1) sum += __shfl_xor_sync(0xffffffffu, sum, o);
    if ((t & 31) == 0) shs[t >> 5] = sum;
    __syncthreads();
    sum = shs[0];
#pragma unroll
    for (int w = 1; w < 8; w++) sum += shs[w];
    const float invs = 1.0f / sum;

#pragma unroll
    for (int j = 0; j < 16; j++) p[t + j * 256] = r[j] * invs;
}

// =====================================================================
// Generic batched fp32 GEMM: C[b][m][n] = alpha * sum_k A(m,k)*B(k,n)
//                                        (+ bias[m]) (+ res[b][m][n])
//   A(m,k) = A[b*a_bs + m*lda_m + k*lda_k]
//   B(k,n) = B[b*b_bs + k*ldb_k + n*ldb_n]
//   C row-major with leading dim ldc (n contiguous).
// AKC=1 means A's k-stride is 1 (k-contiguous), else m-stride is 1.
// BKC=1 means B's k-stride is 1 (k-contiguous), else n-stride is 1.
// Tile: 128x128x8, 256 threads, 8x8 per-thread microtile.
// Requires M%128==0, N%128==0, K%8==0 (true for all uses here).
// =====================================================================
template<int AKC, int BKC>
__global__ __launch_bounds__(256)
void gemm_kernel(const float* __restrict__ A, const float* __restrict__ Bm,
                 float* __restrict__ Cm,
                 int K,
                 int lda_m, int lda_k, size_t a_bs,
                 int ldb_k, int ldb_n, size_t b_bs,
                 int ldc, size_t c_bs,
                 float alpha,
                 const float* __restrict__ bias,
                 const float* __restrict__ res, size_t r_bs)
{
    constexpr int BM = 128, BN = 128, BK = 8;
    __shared__ __align__(16) float As[BK][BM];
    __shared__ __align__(16) float Bs[BK][BN];

    const int bz = blockIdx.z;
    const float* Ap = A  + (size_t)bz * a_bs;
    const float* Bp = Bm + (size_t)bz * b_bs;
    const int m0 = blockIdx.y * BM;
    const int n0 = blockIdx.x * BN;
    const int t  = threadIdx.x;

    float acc[8][8];
#pragma unroll
    for (int i = 0; i < 8; i++)
#pragma unroll
        for (int j = 0; j < 8; j++) acc[i][j] = 0.f;

    const int tx = t & 15;        // n direction
    const int ty = t >> 4;        // m direction

    for (int k0 = 0; k0 < K; k0 += BK) {
        // ---- load A tile (BK x BM) ----
        if (AKC == 0) {
            const int m = (t & 31) * 4;
            const int k = t >> 5;
            float4 v = *(const float4*)(Ap + (size_t)(k0 + k) * lda_k + (m0 + m));
            *(float4*)&As[k][m] = v;
        } else {
            const int m = t >> 1;
            const int k = (t & 1) * 4;
            float4 v = *(const float4*)(Ap + (size_t)(m0 + m) * lda_m + (k0 + k));
            As[k + 0][m] = v.x; As[k + 1][m] = v.y;
            As[k + 2][m] = v.z; As[k + 3][m] = v.w;
        }
        // ---- load B tile (BK x BN) ----
        if (BKC == 0) {
            const int n = (t & 31) * 4;
            const int k = t >> 5;
            float4 v = *(const float4*)(Bp + (size_t)(k0 + k) * ldb_k + (n0 + n));
            *(float4*)&Bs[k][n] = v;
        } else {
            const int n = t >> 1;
            const int k = (t & 1) * 4;
            float4 v = *(const float4*)(Bp + (size_t)(n0 + n) * ldb_n + (k0 + k));
            Bs[k + 0][n] = v.x; Bs[k + 1][n] = v.y;
            Bs[k + 2][n] = v.z; Bs[k + 3][n] = v.w;
        }
        __syncthreads();

#pragma unroll
        for (int k = 0; k < BK; k++) {
            float a[8], bb[8];
            *(float4*)(a)      = *(const float4*)&As[k][ty * 8];
            *(float4*)(a + 4)  = *(const float4*)&As[k][ty * 8 + 4];
            *(float4*)(bb)     = *(const float4*)&Bs[k][tx * 8];
            *(float4*)(bb + 4) = *(const float4*)&Bs[k][tx * 8 + 4];
#pragma unroll
            for (int i = 0; i < 8; i++)
#pragma unroll
                for (int j = 0; j < 8; j++)
                    acc[i][j] = fmaf(a[i], bb[j], acc[i][j]);
        }
        __syncthreads();
    }

    // ---- epilogue ----
    float* Cp = Cm + (size_t)bz * c_bs;
    const float* Rp = res ? (res + (size_t)bz * r_bs) : nullptr;
#pragma unroll
    for (int i = 0; i < 8; i++) {
        const int m = m0 + ty * 8 + i;
        const float bv = bias ? bias[m] : 0.f;
        const size_t rowoff = (size_t)m * ldc + n0 + tx * 8;
#pragma unroll
        for (int j = 0; j < 8; j += 4) {
            float4 o;
            o.x = acc[i][j + 0] * alpha + bv;
            o.y = acc[i][j + 1] * alpha + bv;
            o.z = acc[i][j + 2] * alpha + bv;
            o.w = acc[i][j + 3] * alpha + bv;
            if (Rp) {
                float4 r4 = *(const float4*)(Rp + rowoff + j);
                o.x += r4.x; o.y += r4.y; o.z += r4.z; o.w += r4.w;
            }
            *(float4*)(Cp + rowoff + j) = o;
        }
    }
}

// =====================================================================
// launch
// =====================================================================
extern "C" void kernel_launch(void* const* d_in, const int* in_sizes, int n_in,
                              void* d_out, int out_size)
{
    const float* x  = (const float*)d_in[0];
    const float* gs = (const float*)d_in[1];
    const float* gb = (const float*)d_in[2];
    const float* wq = (const float*)d_in[3];
    const float* bq = (const float*)d_in[4];
    const float* wk = (const float*)d_in[5];
    const float* bk = (const float*)d_in[6];
    const float* wv = (const float*)d_in[7];
    const float* bv = (const float*)d_in[8];
    const float* wp = (const float*)d_in[9];
    const float* bp = (const float*)d_in[10];
    float* out = (float*)d_out;

    float *hn, *q, *k, *v, *s, *ao;
    cudaGetSymbolAddress((void**)&hn, g_hn);
    cudaGetSymbolAddress((void**)&q,  g_q);
    cudaGetSymbolAddress((void**)&k,  g_k);
    cudaGetSymbolAddress((void**)&v,  g_v);
    cudaGetSymbolAddress((void**)&s,  g_s);
    cudaGetSymbolAddress((void**)&ao, g_ao);

    const float attn_scale = 1.0f / sqrtf((float)C);   // 512^-0.5

    // 1. GroupNorm
    groupnorm_kernel<<<BATCH * G, 256>>>(x, gs, gb, hn);

    // 2. q/k/v = W @ hn + b   (M=C, N=HW, K=C); A=W is k-contiguous.
    {
        dim3 grid(HW / 128, C / 128, BATCH);
        gemm_kernel<1, 0><<<grid, 256>>>(wq, hn, q, C,
                                         C, 1, 0,  HW, 1, CBS,  HW, CBS,
                                         1.0f, bq, nullptr, 0);
        gemm_kernel<1, 0><<<grid, 256>>>(wk, hn, k, C,
                                         C, 1, 0,  HW, 1, CBS,  HW, CBS,
                                         1.0f, bk, nullptr, 0);
        gemm_kernel<1, 0><<<grid, 256>>>(wv, hn, v, C,
                                         C, 1, 0,  HW, 1, CBS,  HW, CBS,
                                         1.0f, bv, nullptr, 0);
    }

    // 3. S[b,i,j] = scale * sum_c q[b,c,i] * k[b,c,j]
    //    A(m=i,k=c) = q[c*HW + i]  -> m-contiguous (AKC=0, lda_k=HW)
    //    B(k=c,n=j) = k[c*HW + j]  -> n-contiguous (BKC=0)
    {
        dim3 grid(HW / 128, HW / 128, BATCH);
        gemm_kernel<0, 0><<<grid, 256>>>(q, k, s, C,
                                         1, HW, CBS,  HW, 1, CBS,  HW, SBS,
                                         attn_scale, nullptr, nullptr, 0);
    }

    // 4. softmax over j (rows of S)
    softmax_kernel<<<BATCH * HW, 256>>>(s);

    // 5. ao[b,c,i] = sum_j v[b,c,j] * P[b,i,j]
    //    A(m=c,k=j) = v[c*HW + j]  -> k-contiguous (AKC=1)
    //    B(k=j,n=i) = P[i*HW + j]  -> k-contiguous (BKC=1, ldb_n=HW)
    {
        dim3 grid(HW / 128, C / 128, BATCH);
        gemm_kernel<1, 1><<<grid, 256>>>(v, s, ao, HW,
                                         HW, 1, CBS,  1, HW, SBS,  HW, CBS,
                                         1.0f, nullptr, nullptr, 0);
    }

    // 6. out = wproj @ ao + bproj + x   (residual fused)
    {
        dim3 grid(HW / 128, C / 128, BATCH);
        gemm_kernel<1, 0><<<grid, 256>>>(wp, ao, out, C,
                                         C, 1, 0,  HW, 1, CBS,  HW, CBS,
                                         1.0f, bp, x, CBS);
    }
}

// round 4
// speedup vs baseline: 2.5573x; 2.5573x over previous
#include <cuda_runtime.h>
#include <cstdint>
#include <math.h>

// ---------------- problem constants ----------------
static constexpr int BATCH = 4;
static constexpr int C     = 512;
static constexpr int HW    = 4096;
static constexpr int G     = 32;
static constexpr int CPG   = C / G;          // 16
static constexpr size_t CBS = (size_t)C * HW;
static constexpr size_t SBS = (size_t)HW * HW;

// ---------------- scratch ----------------
__device__ float g_hnt[BATCH * HW * C];          // hn transposed [b][hw][c]
__device__ float g_qt [BATCH * HW * C];          // q  transposed [b][hw][c]
__device__ float g_kt [BATCH * HW * C];          // k  transposed [b][hw][c]
__device__ float g_v  [BATCH * C * HW];          // v  [b][c][hw]
__device__ float g_s  [(size_t)BATCH * HW * HW]; // S  [b][i][j]
__device__ float g_aot[BATCH * HW * C];          // attn out transposed [b][hw][c]

// ---------------- helpers ----------------
__device__ __forceinline__ uint32_t f2tf32(float x) {
    uint32_t r;
    asm("cvt.rna.tf32.f32 %0, %1;" : "=r"(r) : "f"(x));
    return r;
}
__device__ __forceinline__ void cp_async16(uint32_t s, const void* g) {
    asm volatile("cp.async.cg.shared.global [%0], [%1], 16;" :: "r"(s), "l"(g));
}

// ---------------- GroupNorm with transposed output ----------------
__global__ void groupnorm_t_kernel(const float* __restrict__ x,
                                   const float* __restrict__ scale,
                                   const float* __restrict__ bias,
                                   float* __restrict__ out_t)
{
    const int bg = blockIdx.x;
    const int b = bg / G, g = bg % G;
    const int N = CPG * HW;
    const size_t base = ((size_t)b * C + (size_t)g * CPG) * HW;
    const float* xp = x + base;
    const int t = threadIdx.x;

    float s = 0.f, ss = 0.f;
    for (int i = t; i < N; i += 256) {
        float v = xp[i];
        s += v; ss += v * v;
    }
    __shared__ float sh_s[256], sh_q[256];
    sh_s[t] = s; sh_q[t] = ss;
    __syncthreads();
    for (int o = 128; o > 0; o >>= 1) {
        if (t < o) { sh_s[t] += sh_s[t + o]; sh_q[t] += sh_q[t + o]; }
        __syncthreads();
    }
    const float mean = sh_s[0] * (1.0f / N);
    const float var  = sh_q[0] * (1.0f / N) - mean * mean;
    const float inv  = rsqrtf(var + 1e-6f);

    float scl[16], bia[16];
#pragma unroll
    for (int c = 0; c < 16; c++) {
        scl[c] = scale[g * CPG + c] * inv;
        bia[c] = bias[g * CPG + c] - mean * scl[c];
    }

    for (int chunk = 0; chunk < 16; ++chunk) {
        const int n = chunk * 256 + t;
        float vals[16];
#pragma unroll
        for (int c = 0; c < 16; c++)
            vals[c] = xp[c * HW + n] * scl[c] + bia[c];
        float* op = out_t + ((size_t)b * HW + n) * C + g * CPG;
#pragma unroll
        for (int c4 = 0; c4 < 4; c4++)
            *(float4*)(op + c4 * 4) = *(const float4*)(vals + c4 * 4);
    }
}

// ---------------- row softmax (4096 per row, registers) ----------------
__global__ void softmax_kernel(float* __restrict__ sbuf)
{
    const size_t row = blockIdx.x;
    float* p = sbuf + row * (size_t)HW;
    const int t = threadIdx.x;

    float r[16];
    float m = -1e30f;
#pragma unroll
    for (int j = 0; j < 16; j++) { r[j] = p[t + j * 256]; m = fmaxf(m, r[j]); }
    __shared__ float shm[8], shs[8];
#pragma unroll
    for (int o = 16; o > 0; o >>= 1) m = fmaxf(m, __shfl_xor_sync(0xffffffffu, m, o));
    if ((t & 31) == 0) shm[t >> 5] = m;
    __syncthreads();
    m = shm[0];
#pragma unroll
    for (int w = 1; w < 8; w++) m = fmaxf(m, shm[w]);

    float sum = 0.f;
#pragma unroll
    for (int j = 0; j < 16; j++) { r[j] = __expf(r[j] - m); sum += r[j]; }
#pragma unroll
    for (int o = 16; o > 0; o >>= 1) sum += __shfl_xor_sync(0xffffffffu, sum, o);
    if ((t & 31) == 0) shs[t >> 5] = sum;
    __syncthreads();
    sum = shs[0];
#pragma unroll
    for (int w = 1; w < 8; w++) sum += shs[w];
    const float invs = 1.0f / sum;
#pragma unroll
    for (int j = 0; j < 16; j++) p[t + j * 256] = r[j] * invs;
}

// =====================================================================
// tf32 mma.sync GEMM: D[m][n] = alpha * sum_k A[m][k]*B[n][k] (+bias[m]) (+res)
// Both A and B are K-major (k contiguous), row strides lda / ldb.
// TOUT=0: D row-major (ldc), optional bias + residual.
// TOUT=1: D transposed: C[n*ldc + m], optional bias.
// SWAP=1: m-tile indexed by blockIdx.x.
// CTA tile 128x128, BK=16, 256 threads, 8 warps in 2(m) x 4(n), warp tile 64x32.
// Smem row stride 20 floats -> conflict-free mma fragment loads.
// =====================================================================
template<int TOUT, int SWAP>
__global__ void __launch_bounds__(256)
gemm_mma(const float* __restrict__ A, const float* __restrict__ B,
         float* __restrict__ Cm, int K,
         int lda, size_t a_bs, int ldb, size_t b_bs, int ldc, size_t c_bs,
         float alpha, const float* __restrict__ bias,
         const float* __restrict__ res, size_t r_bs)
{
    constexpr int STR = 20;                 // smem row stride (floats)
    constexpr uint32_t BUFB = 128 * STR * 4;// bytes per buffer
    __shared__ float As[2][128 * STR];
    __shared__ float Bs[2][128 * STR];

    const int tid  = threadIdx.x;
    const int wid  = tid >> 5, lane = tid & 31;
    const int gid  = lane >> 2, tid4 = lane & 3;
    const int mbase = (wid & 1) * 64;
    const int nbase = (wid >> 1) * 32;

    int m0, n0;
    if (SWAP) { m0 = blockIdx.x * 128; n0 = blockIdx.y * 128; }
    else      { m0 = blockIdx.y * 128; n0 = blockIdx.x * 128; }
    const float* Ap = A + (size_t)blockIdx.z * a_bs + (size_t)m0 * lda;
    const float* Bp = B + (size_t)blockIdx.z * b_bs + (size_t)n0 * ldb;

    const int lmm = tid >> 2;               // 0..63 (row for loads)
    const int lk4 = tid & 3;                // float4 index within 16-float row
    const uint32_t sA = (uint32_t)__cvta_generic_to_shared(&As[0][0]);
    const uint32_t sB = (uint32_t)__cvta_generic_to_shared(&Bs[0][0]);

    float acc[4][4][4];
#pragma unroll
    for (int i = 0; i < 4; i++)
#pragma unroll
        for (int j = 0; j < 4; j++)
#pragma unroll
            for (int e = 0; e < 4; e++) acc[i][j][e] = 0.f;

    const int niter = K >> 4;

    // prefetch tile 0
    {
#pragma unroll
        for (int j = 0; j < 2; j++) {
            const int m = lmm + j * 64;
            const uint32_t so = (uint32_t)(m * STR + lk4 * 4) * 4u;
            cp_async16(sA + so, Ap + (size_t)m * lda + lk4 * 4);
            cp_async16(sB + so, Bp + (size_t)m * ldb + lk4 * 4);
        }
        asm volatile("cp.async.commit_group;" ::: "memory");
    }

    for (int it = 0; it < niter; ++it) {
        const int buf = it & 1;
        asm volatile("cp.async.wait_group 0;" ::: "memory");
        __syncthreads();

        if (it + 1 < niter) {
            const int k0 = (it + 1) << 4;
            const uint32_t bo = (uint32_t)((it + 1) & 1) * BUFB;
#pragma unroll
            for (int j = 0; j < 2; j++) {
                const int m = lmm + j * 64;
                const uint32_t so = bo + (uint32_t)(m * STR + lk4 * 4) * 4u;
                cp_async16(sA + so, Ap + (size_t)m * lda + k0 + lk4 * 4);
                cp_async16(sB + so, Bp + (size_t)m * ldb + k0 + lk4 * 4);
            }
            asm volatile("cp.async.commit_group;" ::: "memory");
        }

#pragma unroll
        for (int s = 0; s < 2; s++) {
            const int k8 = s * 8;
            uint32_t a[4][4], b[4][2];
#pragma unroll
            for (int mf = 0; mf < 4; mf++) {
                const float* ap = &As[buf][(mbase + mf * 16 + gid) * STR + k8 + tid4];
                a[mf][0] = f2tf32(ap[0]);
                a[mf][1] = f2tf32(ap[8 * STR]);
                a[mf][2] = f2tf32(ap[4]);
                a[mf][3] = f2tf32(ap[8 * STR + 4]);
            }
#pragma unroll
            for (int nf = 0; nf < 4; nf++) {
                const float* bp = &Bs[buf][(nbase + nf * 8 + gid) * STR + k8 + tid4];
                b[nf][0] = f2tf32(bp[0]);
                b[nf][1] = f2tf32(bp[4]);
            }
#pragma unroll
            for (int mf = 0; mf < 4; mf++)
#pragma unroll
                for (int nf = 0; nf < 4; nf++) {
                    asm volatile(
                        "mma.sync.aligned.m16n8k8.row.col.f32.tf32.tf32.f32 "
                        "{%0,%1,%2,%3}, {%4,%5,%6,%7}, {%8,%9}, {%0,%1,%2,%3};"
                        : "+f"(acc[mf][nf][0]), "+f"(acc[mf][nf][1]),
                          "+f"(acc[mf][nf][2]), "+f"(acc[mf][nf][3])
                        : "r"(a[mf][0]), "r"(a[mf][1]), "r"(a[mf][2]), "r"(a[mf][3]),
                          "r"(b[nf][0]), "r"(b[nf][1]));
                }
        }
    }

    // ---- epilogue ----
    float* Cp = Cm + (size_t)blockIdx.z * c_bs;
    const float* Rp = res ? (res + (size_t)blockIdx.z * r_bs) : nullptr;
#pragma unroll
    for (int mf = 0; mf < 4; mf++) {
        const int r0 = m0 + mbase + mf * 16 + gid;
        const int r1 = r0 + 8;
        const float bv0 = bias ? bias[r0] : 0.f;
        const float bv1 = bias ? bias[r1] : 0.f;
#pragma unroll
        for (int nf = 0; nf < 4; nf++) {
            const int cb = n0 + nbase + nf * 8 + tid4 * 2;
            float v00 = acc[mf][nf][0] * alpha + bv0;
            float v01 = acc[mf][nf][1] * alpha + bv0;
            float v10 = acc[mf][nf][2] * alpha + bv1;
            float v11 = acc[mf][nf][3] * alpha + bv1;
            if (TOUT) {
                Cp[(size_t)cb * ldc + r0]       = v00;
                Cp[(size_t)(cb + 1) * ldc + r0] = v01;
                Cp[(size_t)cb * ldc + r1]       = v10;
                Cp[(size_t)(cb + 1) * ldc + r1] = v11;
            } else {
                if (Rp) {
                    v00 += Rp[(size_t)r0 * ldc + cb];
                    v01 += Rp[(size_t)r0 * ldc + cb + 1];
                    v10 += Rp[(size_t)r1 * ldc + cb];
                    v11 += Rp[(size_t)r1 * ldc + cb + 1];
                }
                float2 o0 = make_float2(v00, v01);
                float2 o1 = make_float2(v10, v11);
                *(float2*)&Cp[(size_t)r0 * ldc + cb] = o0;
                *(float2*)&Cp[(size_t)r1 * ldc + cb] = o1;
            }
        }
    }
}

// ---------------- launch ----------------
extern "C" void kernel_launch(void* const* d_in, const int* in_sizes, int n_in,
                              void* d_out, int out_size)
{
    const float* x  = (const float*)d_in[0];
    const float* gs = (const float*)d_in[1];
    const float* gb = (const float*)d_in[2];
    const float* wq = (const float*)d_in[3];
    const float* bq = (const float*)d_in[4];
    const float* wk = (const float*)d_in[5];
    const float* bk = (const float*)d_in[6];
    const float* wv = (const float*)d_in[7];
    const float* bv = (const float*)d_in[8];
    const float* wp = (const float*)d_in[9];
    const float* bp = (const float*)d_in[10];
    float* out = (float*)d_out;

    float *hnt, *qt, *kt, *v, *s, *aot;
    cudaGetSymbolAddress((void**)&hnt, g_hnt);
    cudaGetSymbolAddress((void**)&qt,  g_qt);
    cudaGetSymbolAddress((void**)&kt,  g_kt);
    cudaGetSymbolAddress((void**)&v,   g_v);
    cudaGetSymbolAddress((void**)&s,   g_s);
    cudaGetSymbolAddress((void**)&aot, g_aot);

    const float attn_scale = 1.0f / sqrtf((float)C);

    // 1. GroupNorm -> hn_t [b][hw][c]
    groupnorm_t_kernel<<<BATCH * G, 256>>>(x, gs, gb, hnt);

    // 2. q_t/k_t = (W @ hn)^T ; v = W @ hn
    {
        dim3 grid(HW / 128, C / 128, BATCH);
        gemm_mma<1, 0><<<grid, 256>>>(wq, hnt, qt, C,
                                      C, 0, C, CBS, C, CBS, 1.0f, bq, nullptr, 0);
        gemm_mma<1, 0><<<grid, 256>>>(wk, hnt, kt, C,
                                      C, 0, C, CBS, C, CBS, 1.0f, bk, nullptr, 0);
        gemm_mma<0, 0><<<grid, 256>>>(wv, hnt, v, C,
                                      C, 0, C, CBS, HW, CBS, 1.0f, bv, nullptr, 0);
    }

    // 3. S[b][i][j] = scale * q_t[i,:] . k_t[j,:]
    {
        dim3 grid(HW / 128, HW / 128, BATCH);
        gemm_mma<0, 0><<<grid, 256>>>(qt, kt, s, C,
                                      C, CBS, C, CBS, HW, SBS,
                                      attn_scale, nullptr, nullptr, 0);
    }

    // 4. softmax rows of S
    softmax_kernel<<<BATCH * HW, 256>>>(s);

    // 5. ao_t[b][i][c] = sum_j v[c][j] * P[i][j]
    {
        dim3 grid(C / 128, HW / 128, BATCH);
        gemm_mma<1, 1><<<grid, 256>>>(v, s, aot, HW,
                                      HW, CBS, HW, SBS, C, CBS,
                                      1.0f, nullptr, nullptr, 0);
    }

    // 6. out = wp @ ao + bp + x
    {
        dim3 grid(HW / 128, C / 128, BATCH);
        gemm_mma<0, 0><<<grid, 256>>>(wp, aot, out, C,
                                      C, 0, C, CBS, HW, CBS,
                                      1.0f, bp, x, CBS);
    }
}

// round 5
// speedup vs baseline: 2.9929x; 1.1704x over previous
#include <cuda_runtime.h>
#include <cstdint>
#include <math.h>

// ---------------- problem constants ----------------
static constexpr int BATCH = 4;
static constexpr int C     = 512;
static constexpr int HW    = 4096;
static constexpr int G     = 32;
static constexpr int CPG   = C / G;          // 16
static constexpr size_t CBS = (size_t)C * HW;
static constexpr size_t SBS = (size_t)HW * HW;

// ---------------- scratch ----------------
__device__ float g_hnt[BATCH * HW * C];          // hn transposed [b][hw][c] (tf32-rounded)
__device__ float g_qt [BATCH * HW * C];          // q transposed (tf32-rounded)
__device__ float g_kt [BATCH * HW * C];          // k transposed (tf32-rounded)
__device__ float g_v  [BATCH * C * HW];          // v (tf32-rounded)
__device__ float g_s  [(size_t)BATCH * HW * HW]; // S logits fp32 / probs tf32-rounded
__device__ float g_aot[BATCH * HW * C];          // attn out transposed (tf32-rounded)
__device__ float g_w4 [4 * C * C];               // rounded wq,wk,wv,wproj

// ---------------- helpers ----------------
__device__ __forceinline__ uint32_t f2tf32(float x) {
    uint32_t r;
    asm("cvt.rna.tf32.f32 %0, %1;" : "=r"(r) : "f"(x));
    return r;
}
__device__ __forceinline__ float rnd_tf32(float x) {
    return __uint_as_float(f2tf32(x));
}
__device__ __forceinline__ void cp_async16(uint32_t s, const void* g) {
    asm volatile("cp.async.cg.shared.global [%0], [%1], 16;" :: "r"(s), "l"(g));
}

// ---------------- round the 4 weight matrices into scratch ----------------
__global__ void round_w_kernel(const float* __restrict__ w0, const float* __restrict__ w1,
                               const float* __restrict__ w2, const float* __restrict__ w3,
                               float* __restrict__ out)
{
    const int which = blockIdx.y;
    const float* src = which == 0 ? w0 : which == 1 ? w1 : which == 2 ? w2 : w3;
    float* dst = out + (size_t)which * C * C;
    const int i = (blockIdx.x * 256 + threadIdx.x) * 4;
    float4 v = *(const float4*)(src + i);
    v.x = rnd_tf32(v.x); v.y = rnd_tf32(v.y);
    v.z = rnd_tf32(v.z); v.w = rnd_tf32(v.w);
    *(float4*)(dst + i) = v;
}

// ---------------- GroupNorm with transposed, tf32-rounded output ----------------
__global__ void groupnorm_t_kernel(const float* __restrict__ x,
                                   const float* __restrict__ scale,
                                   const float* __restrict__ bias,
                                   float* __restrict__ out_t)
{
    const int bg = blockIdx.x;
    const int b = bg / G, g = bg % G;
    const int N = CPG * HW;
    const size_t base = ((size_t)b * C + (size_t)g * CPG) * HW;
    const float* xp = x + base;
    const int t = threadIdx.x;

    float s = 0.f, ss = 0.f;
    for (int i = t; i < N; i += 256) {
        float v = xp[i];
        s += v; ss += v * v;
    }
    __shared__ float sh_s[256], sh_q[256];
    sh_s[t] = s; sh_q[t] = ss;
    __syncthreads();
    for (int o = 128; o > 0; o >>= 1) {
        if (t < o) { sh_s[t] += sh_s[t + o]; sh_q[t] += sh_q[t + o]; }
        __syncthreads();
    }
    const float mean = sh_s[0] * (1.0f / N);
    const float var  = sh_q[0] * (1.0f / N) - mean * mean;
    const float inv  = rsqrtf(var + 1e-6f);

    float scl[16], bia[16];
#pragma unroll
    for (int c = 0; c < 16; c++) {
        scl[c] = scale[g * CPG + c] * inv;
        bia[c] = bias[g * CPG + c] - mean * scl[c];
    }

    for (int chunk = 0; chunk < 16; ++chunk) {
        const int n = chunk * 256 + t;
        float vals[16];
#pragma unroll
        for (int c = 0; c < 16; c++)
            vals[c] = rnd_tf32(xp[c * HW + n] * scl[c] + bia[c]);
        float* op = out_t + ((size_t)b * HW + n) * C + g * CPG;
#pragma unroll
        for (int c4 = 0; c4 < 4; c4++)
            *(float4*)(op + c4 * 4) = *(const float4*)(vals + c4 * 4);
    }
}

// ---------------- row softmax (tf32-rounded probability output) ----------------
__global__ void softmax_kernel(float* __restrict__ sbuf)
{
    const size_t row = blockIdx.x;
    float* p = sbuf + row * (size_t)HW;
    const int t = threadIdx.x;

    float r[16];
    float m = -1e30f;
#pragma unroll
    for (int j = 0; j < 16; j++) { r[j] = p[t + j * 256]; m = fmaxf(m, r[j]); }
    __shared__ float shm[8], shs[8];
#pragma unroll
    for (int o = 16; o > 0; o >>= 1) m = fmaxf(m, __shfl_xor_sync(0xffffffffu, m, o));
    if ((t & 31) == 0) shm[t >> 5] = m;
    __syncthreads();
    m = shm[0];
#pragma unroll
    for (int w = 1; w < 8; w++) m = fmaxf(m, shm[w]);

    float sum = 0.f;
#pragma unroll
    for (int j = 0; j < 16; j++) { r[j] = __expf(r[j] - m); sum += r[j]; }
#pragma unroll
    for (int o = 16; o > 0; o >>= 1) sum += __shfl_xor_sync(0xffffffffu, sum, o);
    if ((t & 31) == 0) shs[t >> 5] = sum;
    __syncthreads();
    sum = shs[0];
#pragma unroll
    for (int w = 1; w < 8; w++) sum += shs[w];
    const float invs = 1.0f / sum;
#pragma unroll
    for (int j = 0; j < 16; j++) p[t + j * 256] = rnd_tf32(r[j] * invs);
}

// =====================================================================
// tf32 mma.sync GEMM. Inputs must already be tf32-rounded fp32 bit patterns.
// D[m][n] = alpha * sum_k A[m][k]*B[n][k] (+bias[m]) (+res)
// TOUT=0: row-major out; TOUT=1: transposed out C[n*ldc+m].
// RND=1: round outputs to tf32 (for GEMM-consumed intermediates).
// SWAP=1: m-tile from blockIdx.x.
// CTA 128x128, BK=16, 256 thr, 8 warps (2m x 4n), warp tile 64x32.
// =====================================================================
template<int TOUT, int SWAP, int RND>
__global__ void __launch_bounds__(256, 2)
gemm_mma(const float* __restrict__ A, const float* __restrict__ B,
         float* __restrict__ Cm, int K,
         int lda, size_t a_bs, int ldb, size_t b_bs, int ldc, size_t c_bs,
         float alpha, const float* __restrict__ bias,
         const float* __restrict__ res, size_t r_bs)
{
    constexpr int STR = 20;
    constexpr uint32_t BUFB = 128 * STR * 4;
    __shared__ float As[2][128 * STR];
    __shared__ float Bs[2][128 * STR];

    const int tid  = threadIdx.x;
    const int wid  = tid >> 5, lane = tid & 31;
    const int gid  = lane >> 2, tid4 = lane & 3;
    const int mbase = (wid & 1) * 64;
    const int nbase = (wid >> 1) * 32;

    int m0, n0;
    if (SWAP) { m0 = blockIdx.x * 128; n0 = blockIdx.y * 128; }
    else      { m0 = blockIdx.y * 128; n0 = blockIdx.x * 128; }
    const float* Ap = A + (size_t)blockIdx.z * a_bs + (size_t)m0 * lda;
    const float* Bp = B + (size_t)blockIdx.z * b_bs + (size_t)n0 * ldb;

    const int lmm = tid >> 2;
    const int lk4 = tid & 3;
    const uint32_t sA = (uint32_t)__cvta_generic_to_shared(&As[0][0]);
    const uint32_t sB = (uint32_t)__cvta_generic_to_shared(&Bs[0][0]);

    float acc[4][4][4];
#pragma unroll
    for (int i = 0; i < 4; i++)
#pragma unroll
        for (int j = 0; j < 4; j++)
#pragma unroll
            for (int e = 0; e < 4; e++) acc[i][j][e] = 0.f;

    const int niter = K >> 4;

    {
#pragma unroll
        for (int j = 0; j < 2; j++) {
            const int m = lmm + j * 64;
            const uint32_t so = (uint32_t)(m * STR + lk4 * 4) * 4u;
            cp_async16(sA + so, Ap + (size_t)m * lda + lk4 * 4);
            cp_async16(sB + so, Bp + (size_t)m * ldb + lk4 * 4);
        }
        asm volatile("cp.async.commit_group;" ::: "memory");
    }

    for (int it = 0; it < niter; ++it) {
        const int buf = it & 1;
        asm volatile("cp.async.wait_group 0;" ::: "memory");
        __syncthreads();

        if (it + 1 < niter) {
            const int k0 = (it + 1) << 4;
            const uint32_t bo = (uint32_t)((it + 1) & 1) * BUFB;
#pragma unroll
            for (int j = 0; j < 2; j++) {
                const int m = lmm + j * 64;
                const uint32_t so = bo + (uint32_t)(m * STR + lk4 * 4) * 4u;
                cp_async16(sA + so, Ap + (size_t)m * lda + k0 + lk4 * 4);
                cp_async16(sB + so, Bp + (size_t)m * ldb + k0 + lk4 * 4);
            }
            asm volatile("cp.async.commit_group;" ::: "memory");
        }

#pragma unroll
        for (int s = 0; s < 2; s++) {
            const int k8 = s * 8;
            uint32_t a[4][4], b[4][2];
#pragma unroll
            for (int mf = 0; mf < 4; mf++) {
                const uint32_t* ap = (const uint32_t*)
                    &As[buf][(mbase + mf * 16 + gid) * STR + k8 + tid4];
                a[mf][0] = ap[0];
                a[mf][1] = ap[8 * STR];
                a[mf][2] = ap[4];
                a[mf][3] = ap[8 * STR + 4];
            }
#pragma unroll
            for (int nf = 0; nf < 4; nf++) {
                const uint32_t* bp = (const uint32_t*)
                    &Bs[buf][(nbase + nf * 8 + gid) * STR + k8 + tid4];
                b[nf][0] = bp[0];
                b[nf][1] = bp[4];
            }
#pragma unroll
            for (int mf = 0; mf < 4; mf++)
#pragma unroll
                for (int nf = 0; nf < 4; nf++) {
                    asm volatile(
                        "mma.sync.aligned.m16n8k8.row.col.f32.tf32.tf32.f32 "
                        "{%0,%1,%2,%3}, {%4,%5,%6,%7}, {%8,%9}, {%0,%1,%2,%3};"
                        : "+f"(acc[mf][nf][0]), "+f"(acc[mf][nf][1]),
                          "+f"(acc[mf][nf][2]), "+f"(acc[mf][nf][3])
                        : "r"(a[mf][0]), "r"(a[mf][1]), "r"(a[mf][2]), "r"(a[mf][3]),
                          "r"(b[nf][0]), "r"(b[nf][1]));
                }
        }
    }

    // ---- epilogue ----
    float* Cp = Cm + (size_t)blockIdx.z * c_bs;
    const float* Rp = res ? (res + (size_t)blockIdx.z * r_bs) : nullptr;
#pragma unroll
    for (int mf = 0; mf < 4; mf++) {
        const int r0 = m0 + mbase + mf * 16 + gid;
        const int r1 = r0 + 8;
        const float bv0 = bias ? bias[r0] : 0.f;
        const float bv1 = bias ? bias[r1] : 0.f;
#pragma unroll
        for (int nf = 0; nf < 4; nf++) {
            const int cb = n0 + nbase + nf * 8 + tid4 * 2;
            float v00 = acc[mf][nf][0] * alpha + bv0;
            float v01 = acc[mf][nf][1] * alpha + bv0;
            float v10 = acc[mf][nf][2] * alpha + bv1;
            float v11 = acc[mf][nf][3] * alpha + bv1;
            if (RND) {
                v00 = rnd_tf32(v00); v01 = rnd_tf32(v01);
                v10 = rnd_tf32(v10); v11 = rnd_tf32(v11);
            }
            if (TOUT) {
                Cp[(size_t)cb * ldc + r0]       = v00;
                Cp[(size_t)(cb + 1) * ldc + r0] = v01;
                Cp[(size_t)cb * ldc + r1]       = v10;
                Cp[(size_t)(cb + 1) * ldc + r1] = v11;
            } else {
                if (Rp) {
                    v00 += Rp[(size_t)r0 * ldc + cb];
                    v01 += Rp[(size_t)r0 * ldc + cb + 1];
                    v10 += Rp[(size_t)r1 * ldc + cb];
                    v11 += Rp[(size_t)r1 * ldc + cb + 1];
                }
                *(float2*)&Cp[(size_t)r0 * ldc + cb] = make_float2(v00, v01);
                *(float2*)&Cp[(size_t)r1 * ldc + cb] = make_float2(v10, v11);
            }
        }
    }
}

// ---------------- launch ----------------
extern "C" void kernel_launch(void* const* d_in, const int* in_sizes, int n_in,
                              void* d_out, int out_size)
{
    const float* x  = (const float*)d_in[0];
    const float* gs = (const float*)d_in[1];
    const float* gb = (const float*)d_in[2];
    const float* wq = (const float*)d_in[3];
    const float* bq = (const float*)d_in[4];
    const float* wk = (const float*)d_in[5];
    const float* bk = (const float*)d_in[6];
    const float* wv = (const float*)d_in[7];
    const float* bv = (const float*)d_in[8];
    const float* wp = (const float*)d_in[9];
    const float* bp = (const float*)d_in[10];
    float* out = (float*)d_out;

    float *hnt, *qt, *kt, *v, *s, *aot, *w4;
    cudaGetSymbolAddress((void**)&hnt, g_hnt);
    cudaGetSymbolAddress((void**)&qt,  g_qt);
    cudaGetSymbolAddress((void**)&kt,  g_kt);
    cudaGetSymbolAddress((void**)&v,   g_v);
    cudaGetSymbolAddress((void**)&s,   g_s);
    cudaGetSymbolAddress((void**)&aot, g_aot);
    cudaGetSymbolAddress((void**)&w4,  g_w4);

    const float* rwq = w4;
    const float* rwk = w4 + (size_t)C * C;
    const float* rwv = w4 + 2 * (size_t)C * C;
    const float* rwp = w4 + 3 * (size_t)C * C;

    const float attn_scale = 1.0f / sqrtf((float)C);

    // 0. round weights to tf32 (once per launch; cheap)
    {
        dim3 grid(C * C / (256 * 4), 4);
        round_w_kernel<<<grid, 256>>>(wq, wk, wv, wp, w4);
    }

    // 1. GroupNorm -> hn_t [b][hw][c], tf32-rounded
    groupnorm_t_kernel<<<BATCH * G, 256>>>(x, gs, gb, hnt);

    // 2. q_t/k_t = (W @ hn)^T ; v = W @ hn   (all outputs tf32-rounded)
    {
        dim3 grid(HW / 128, C / 128, BATCH);
        gemm_mma<1, 0, 1><<<grid, 256>>>(rwq, hnt, qt, C,
                                         C, 0, C, CBS, C, CBS, 1.0f, bq, nullptr, 0);
        gemm_mma<1, 0, 1><<<grid, 256>>>(rwk, hnt, kt, C,
                                         C, 0, C, CBS, C, CBS, 1.0f, bk, nullptr, 0);
        gemm_mma<0, 0, 1><<<grid, 256>>>(rwv, hnt, v, C,
                                         C, 0, C, CBS, HW, CBS, 1.0f, bv, nullptr, 0);
    }

    // 3. S logits (fp32, not rounded; softmax rounds the probs)
    {
        dim3 grid(HW / 128, HW / 128, BATCH);
        gemm_mma<0, 0, 0><<<grid, 256>>>(qt, kt, s, C,
                                         C, CBS, C, CBS, HW, SBS,
                                         attn_scale, nullptr, nullptr, 0);
    }

    // 4. softmax rows of S -> tf32-rounded probs
    softmax_kernel<<<BATCH * HW, 256>>>(s);

    // 5. ao_t[b][i][c] = sum_j v[c][j] * P[i][j]  (tf32-rounded out)
    {
        dim3 grid(C / 128, HW / 128, BATCH);
        gemm_mma<1, 1, 1><<<grid, 256>>>(v, s, aot, HW,
                                         HW, CBS, HW, SBS, C, CBS,
                                         1.0f, nullptr, nullptr, 0);
    }

    // 6. out = wp @ ao + bp + x   (fp32 epilogue, no rounding)
    {
        dim3 grid(HW / 128, C / 128, BATCH);
        gemm_mma<0, 0, 0><<<grid, 256>>>(rwp, aot, out, C,
                                         C, 0, C, CBS, HW, CBS,
                                         1.0f, bp, x, CBS);
    }
}

// round 6
// speedup vs baseline: 3.2926x; 1.1001x over previous
#include <cuda_runtime.h>
#include <cstdint>
#include <math.h>

// ---------------- problem constants ----------------
static constexpr int BATCH = 4;
static constexpr int C     = 512;
static constexpr int HW    = 4096;
static constexpr int G     = 32;
static constexpr int CPG   = C / G;          // 16
static constexpr size_t CBS = (size_t)C * HW;
static constexpr size_t SBS = (size_t)HW * HW;

// ---------------- scratch ----------------
__device__ float g_hnt[BATCH * HW * C];          // hn transposed [b][hw][c] (tf32-rounded)
__device__ float g_qt [BATCH * HW * C];          // q transposed (tf32-rounded)
__device__ float g_kt [BATCH * HW * C];          // k transposed (tf32-rounded)
__device__ float g_v  [BATCH * C * HW];          // v (tf32-rounded)
__device__ float g_s  [(size_t)BATCH * HW * HW]; // S logits fp32 / probs tf32-rounded
__device__ float g_aot[BATCH * HW * C];          // attn out transposed (tf32-rounded)
__device__ float g_w4 [4 * C * C];               // rounded wq,wk,wv,wproj

// ---------------- helpers ----------------
__device__ __forceinline__ uint32_t f2tf32(float x) {
    uint32_t r;
    asm("cvt.rna.tf32.f32 %0, %1;" : "=r"(r) : "f"(x));
    return r;
}
__device__ __forceinline__ float rnd_tf32(float x) {
    return __uint_as_float(f2tf32(x));
}
__device__ __forceinline__ void cp_async16(uint32_t s, const void* g) {
    asm volatile("cp.async.cg.shared.global [%0], [%1], 16;" :: "r"(s), "l"(g));
}
__device__ __forceinline__ void ldsm_x4(uint32_t& r0, uint32_t& r1, uint32_t& r2,
                                        uint32_t& r3, uint32_t addr) {
    asm volatile("ldmatrix.sync.aligned.m8n8.x4.shared.b16 {%0,%1,%2,%3}, [%4];"
                 : "=r"(r0), "=r"(r1), "=r"(r2), "=r"(r3) : "r"(addr));
}
__device__ __forceinline__ void ldsm_x2(uint32_t& r0, uint32_t& r1, uint32_t addr) {
    asm volatile("ldmatrix.sync.aligned.m8n8.x2.shared.b16 {%0,%1}, [%2];"
                 : "=r"(r0), "=r"(r1) : "r"(addr));
}

// ---------------- round the 4 weight matrices into scratch ----------------
__global__ void round_w_kernel(const float* __restrict__ w0, const float* __restrict__ w1,
                               const float* __restrict__ w2, const float* __restrict__ w3,
                               float* __restrict__ out)
{
    const int which = blockIdx.y;
    const float* src = which == 0 ? w0 : which == 1 ? w1 : which == 2 ? w2 : w3;
    float* dst = out + (size_t)which * C * C;
    const int i = (blockIdx.x * 256 + threadIdx.x) * 4;
    float4 v = *(const float4*)(src + i);
    v.x = rnd_tf32(v.x); v.y = rnd_tf32(v.y);
    v.z = rnd_tf32(v.z); v.w = rnd_tf32(v.w);
    *(float4*)(dst + i) = v;
}

// ---------------- GroupNorm with transposed, tf32-rounded output ----------------
__global__ void groupnorm_t_kernel(const float* __restrict__ x,
                                   const float* __restrict__ scale,
                                   const float* __restrict__ bias,
                                   float* __restrict__ out_t)
{
    const int bg = blockIdx.x;
    const int b = bg / G, g = bg % G;
    const int N = CPG * HW;
    const size_t base = ((size_t)b * C + (size_t)g * CPG) * HW;
    const float* xp = x + base;
    const int t = threadIdx.x;

    float s = 0.f, ss = 0.f;
    for (int i = t; i < N; i += 256) {
        float v = xp[i];
        s += v; ss += v * v;
    }
    __shared__ float sh_s[256], sh_q[256];
    sh_s[t] = s; sh_q[t] = ss;
    __syncthreads();
    for (int o = 128; o > 0; o >>= 1) {
        if (t < o) { sh_s[t] += sh_s[t + o]; sh_q[t] += sh_q[t + o]; }
        __syncthreads();
    }
    const float mean = sh_s[0] * (1.0f / N);
    const float var  = sh_q[0] * (1.0f / N) - mean * mean;
    const float inv  = rsqrtf(var + 1e-6f);

    float scl[16], bia[16];
#pragma unroll
    for (int c = 0; c < 16; c++) {
        scl[c] = scale[g * CPG + c] * inv;
        bia[c] = bias[g * CPG + c] - mean * scl[c];
    }

    for (int chunk = 0; chunk < 16; ++chunk) {
        const int n = chunk * 256 + t;
        float vals[16];
#pragma unroll
        for (int c = 0; c < 16; c++)
            vals[c] = rnd_tf32(xp[c * HW + n] * scl[c] + bia[c]);
        float* op = out_t + ((size_t)b * HW + n) * C + g * CPG;
#pragma unroll
        for (int c4 = 0; c4 < 4; c4++)
            *(float4*)(op + c4 * 4) = *(const float4*)(vals + c4 * 4);
    }
}

// ---------------- row softmax (tf32-rounded probability output) ----------------
__global__ void softmax_kernel(float* __restrict__ sbuf)
{
    const size_t row = blockIdx.x;
    float* p = sbuf + row * (size_t)HW;
    const int t = threadIdx.x;

    float r[16];
    float m = -1e30f;
#pragma unroll
    for (int j = 0; j < 16; j++) { r[j] = p[t + j * 256]; m = fmaxf(m, r[j]); }
    __shared__ float shm[8], shs[8];
#pragma unroll
    for (int o = 16; o > 0; o >>= 1) m = fmaxf(m, __shfl_xor_sync(0xffffffffu, m, o));
    if ((t & 31) == 0) shm[t >> 5] = m;
    __syncthreads();
    m = shm[0];
#pragma unroll
    for (int w = 1; w < 8; w++) m = fmaxf(m, shm[w]);

    float sum = 0.f;
#pragma unroll
    for (int j = 0; j < 16; j++) { r[j] = __expf(r[j] - m); sum += r[j]; }
#pragma unroll
    for (int o = 16; o > 0; o >>= 1) sum += __shfl_xor_sync(0xffffffffu, sum, o);
    if ((t & 31) == 0) shs[t >> 5] = sum;
    __syncthreads();
    sum = shs[0];
#pragma unroll
    for (int w = 1; w < 8; w++) sum += shs[w];
    const float invs = 1.0f / sum;
#pragma unroll
    for (int j = 0; j < 16; j++) p[t + j * 256] = rnd_tf32(r[j] * invs);
}

// =====================================================================
// tf32 mma.sync GEMM; fragment loads via ldmatrix. Inputs pre-rounded.
// D[m][n] = alpha * sum_k A[m][k]*B[n][k] (+bias[m]) (+res)
// TOUT: 0 row-major out, 1 transposed out. RND: round outputs to tf32.
// SWAP: m-tile from blockIdx.x.
// CTA 128x128, BK=16, 256 thr, 8 warps (2m x 4n), warp tile 64x32.
// =====================================================================
template<int TOUT, int SWAP, int RND>
__global__ void __launch_bounds__(256, 2)
gemm_mma(const float* __restrict__ A, const float* __restrict__ B,
         float* __restrict__ Cm, int K,
         int lda, size_t a_bs, int ldb, size_t b_bs, int ldc, size_t c_bs,
         float alpha, const float* __restrict__ bias,
         const float* __restrict__ res, size_t r_bs)
{
    constexpr int STR = 20;
    constexpr uint32_t BUFB = 128 * STR * 4;
    __shared__ float As[2][128 * STR];
    __shared__ float Bs[2][128 * STR];

    const int tid  = threadIdx.x;
    const int wid  = tid >> 5, lane = tid & 31;
    const int gid  = lane >> 2, tid4 = lane & 3;
    const int mbase = (wid & 1) * 64;
    const int nbase = (wid >> 1) * 32;

    int m0, n0;
    if (SWAP) { m0 = blockIdx.x * 128; n0 = blockIdx.y * 128; }
    else      { m0 = blockIdx.y * 128; n0 = blockIdx.x * 128; }
    const float* Ap = A + (size_t)blockIdx.z * a_bs + (size_t)m0 * lda;
    const float* Bp = B + (size_t)blockIdx.z * b_bs + (size_t)n0 * ldb;

    const int lmm = tid >> 2;
    const int lk4 = tid & 3;
    const uint32_t sA = (uint32_t)__cvta_generic_to_shared(&As[0][0]);
    const uint32_t sB = (uint32_t)__cvta_generic_to_shared(&Bs[0][0]);

    // ldmatrix per-lane base addresses (loop-invariant)
    // A x4: matrices {rows0-7,k0-3},{rows8-15,k0-3},{rows0-7,k4-7},{rows8-15,k4-7}
    const int rowA = mbase + (lane & 7) + ((lane >> 3) & 1) * 8;
    const int colA = (lane >> 4) * 4;
    const uint32_t aBase = sA + (uint32_t)(rowA * STR + colA) * 4u;
    // B x2: matrices {n-rows0-7,k0-3},{n-rows0-7,k4-7} (addr lanes 0-15)
    const int rowB = nbase + (lane & 7);
    const int colB = ((lane >> 3) & 1) * 4;
    const uint32_t bBase = sB + (uint32_t)(rowB * STR + colB) * 4u;

    float acc[4][4][4];
#pragma unroll
    for (int i = 0; i < 4; i++)
#pragma unroll
        for (int j = 0; j < 4; j++)
#pragma unroll
            for (int e = 0; e < 4; e++) acc[i][j][e] = 0.f;

    const int niter = K >> 4;

    {
#pragma unroll
        for (int j = 0; j < 2; j++) {
            const int m = lmm + j * 64;
            const uint32_t so = (uint32_t)(m * STR + lk4 * 4) * 4u;
            cp_async16(sA + so, Ap + (size_t)m * lda + lk4 * 4);
            cp_async16(sB + so, Bp + (size_t)m * ldb + lk4 * 4);
        }
        asm volatile("cp.async.commit_group;" ::: "memory");
    }

    for (int it = 0; it < niter; ++it) {
        const uint32_t bufo = (uint32_t)(it & 1) * BUFB;
        asm volatile("cp.async.wait_group 0;" ::: "memory");
        __syncthreads();

        if (it + 1 < niter) {
            const int k0 = (it + 1) << 4;
            const uint32_t bo = (uint32_t)((it + 1) & 1) * BUFB;
#pragma unroll
            for (int j = 0; j < 2; j++) {
                const int m = lmm + j * 64;
                const uint32_t so = bo + (uint32_t)(m * STR + lk4 * 4) * 4u;
                cp_async16(sA + so, Ap + (size_t)m * lda + k0 + lk4 * 4);
                cp_async16(sB + so, Bp + (size_t)m * ldb + k0 + lk4 * 4);
            }
            asm volatile("cp.async.commit_group;" ::: "memory");
        }

#pragma unroll
        for (int s = 0; s < 2; s++) {
            const uint32_t k8o = bufo + (uint32_t)(s * 8) * 4u;
            uint32_t a[4][4], b[4][2];
#pragma unroll
            for (int mf = 0; mf < 4; mf++)
                ldsm_x4(a[mf][0], a[mf][1], a[mf][2], a[mf][3],
                        aBase + k8o + (uint32_t)(mf * 16 * STR) * 4u);
#pragma unroll
            for (int nf = 0; nf < 4; nf++)
                ldsm_x2(b[nf][0], b[nf][1],
                        bBase + k8o + (uint32_t)(nf * 8 * STR) * 4u);
#pragma unroll
            for (int mf = 0; mf < 4; mf++)
#pragma unroll
                for (int nf = 0; nf < 4; nf++) {
                    asm volatile(
                        "mma.sync.aligned.m16n8k8.row.col.f32.tf32.tf32.f32 "
                        "{%0,%1,%2,%3}, {%4,%5,%6,%7}, {%8,%9}, {%0,%1,%2,%3};"
                        : "+f"(acc[mf][nf][0]), "+f"(acc[mf][nf][1]),
                          "+f"(acc[mf][nf][2]), "+f"(acc[mf][nf][3])
                        : "r"(a[mf][0]), "r"(a[mf][1]), "r"(a[mf][2]), "r"(a[mf][3]),
                          "r"(b[nf][0]), "r"(b[nf][1]));
                }
        }
    }

    // ---- epilogue ----
    float* Cp = Cm + (size_t)blockIdx.z * c_bs;
    const float* Rp = res ? (res + (size_t)blockIdx.z * r_bs) : nullptr;
#pragma unroll
    for (int mf = 0; mf < 4; mf++) {
        const int r0 = m0 + mbase + mf * 16 + gid;
        const int r1 = r0 + 8;
        const float bv0 = bias ? bias[r0] : 0.f;
        const float bv1 = bias ? bias[r1] : 0.f;
#pragma unroll
        for (int nf = 0; nf < 4; nf++) {
            const int cb = n0 + nbase + nf * 8 + tid4 * 2;
            float v00 = acc[mf][nf][0] * alpha + bv0;
            float v01 = acc[mf][nf][1] * alpha + bv0;
            float v10 = acc[mf][nf][2] * alpha + bv1;
            float v11 = acc[mf][nf][3] * alpha + bv1;
            if (RND) {
                v00 = rnd_tf32(v00); v01 = rnd_tf32(v01);
                v10 = rnd_tf32(v10); v11 = rnd_tf32(v11);
            }
            if (TOUT) {
                Cp[(size_t)cb * ldc + r0]       = v00;
                Cp[(size_t)(cb + 1) * ldc + r0] = v01;
                Cp[(size_t)cb * ldc + r1]       = v10;
                Cp[(size_t)(cb + 1) * ldc + r1] = v11;
            } else {
                if (Rp) {
                    v00 += Rp[(size_t)r0 * ldc + cb];
                    v01 += Rp[(size_t)r0 * ldc + cb + 1];
                    v10 += Rp[(size_t)r1 * ldc + cb];
                    v11 += Rp[(size_t)r1 * ldc + cb + 1];
                }
                *(float2*)&Cp[(size_t)r0 * ldc + cb] = make_float2(v00, v01);
                *(float2*)&Cp[(size_t)r1 * ldc + cb] = make_float2(v10, v11);
            }
        }
    }
}

// ---------------- launch ----------------
extern "C" void kernel_launch(void* const* d_in, const int* in_sizes, int n_in,
                              void* d_out, int out_size)
{
    const float* x  = (const float*)d_in[0];
    const float* gs = (const float*)d_in[1];
    const float* gb = (const float*)d_in[2];
    const float* wq = (const float*)d_in[3];
    const float* bq = (const float*)d_in[4];
    const float* wk = (const float*)d_in[5];
    const float* bk = (const float*)d_in[6];
    const float* wv = (const float*)d_in[7];
    const float* bv = (const float*)d_in[8];
    const float* wp = (const float*)d_in[9];
    const float* bp = (const float*)d_in[10];
    float* out = (float*)d_out;

    float *hnt, *qt, *kt, *v, *s, *aot, *w4;
    cudaGetSymbolAddress((void**)&hnt, g_hnt);
    cudaGetSymbolAddress((void**)&qt,  g_qt);
    cudaGetSymbolAddress((void**)&kt,  g_kt);
    cudaGetSymbolAddress((void**)&v,   g_v);
    cudaGetSymbolAddress((void**)&s,   g_s);
    cudaGetSymbolAddress((void**)&aot, g_aot);
    cudaGetSymbolAddress((void**)&w4,  g_w4);

    const float* rwq = w4;
    const float* rwk = w4 + (size_t)C * C;
    const float* rwv = w4 + 2 * (size_t)C * C;
    const float* rwp = w4 + 3 * (size_t)C * C;

    const float attn_scale = 1.0f / sqrtf((float)C);

    // 0. round weights to tf32
    {
        dim3 grid(C * C / (256 * 4), 4);
        round_w_kernel<<<grid, 256>>>(wq, wk, wv, wp, w4);
    }

    // 1. GroupNorm -> hn_t [b][hw][c], tf32-rounded
    groupnorm_t_kernel<<<BATCH * G, 256>>>(x, gs, gb, hnt);

    // 2. q_t/k_t = (W @ hn)^T ; v = W @ hn
    {
        dim3 grid(HW / 128, C / 128, BATCH);
        gemm_mma<1, 0, 1><<<grid, 256>>>(rwq, hnt, qt, C,
                                         C, 0, C, CBS, C, CBS, 1.0f, bq, nullptr, 0);
        gemm_mma<1, 0, 1><<<grid, 256>>>(rwk, hnt, kt, C,
                                         C, 0, C, CBS, C, CBS, 1.0f, bk, nullptr, 0);
        gemm_mma<0, 0, 1><<<grid, 256>>>(rwv, hnt, v, C,
                                         C, 0, C, CBS, HW, CBS, 1.0f, bv, nullptr, 0);
    }

    // 3. S logits (fp32)
    {
        dim3 grid(HW / 128, HW / 128, BATCH);
        gemm_mma<0, 0, 0><<<grid, 256>>>(qt, kt, s, C,
                                         C, CBS, C, CBS, HW, SBS,
                                         attn_scale, nullptr, nullptr, 0);
    }

    // 4. softmax rows of S -> tf32-rounded probs
    softmax_kernel<<<BATCH * HW, 256>>>(s);

    // 5. ao_t[b][i][c] = sum_j v[c][j] * P[i][j]
    {
        dim3 grid(C / 128, HW / 128, BATCH);
        gemm_mma<1, 1, 1><<<grid, 256>>>(v, s, aot, HW,
                                         HW, CBS, HW, SBS, C, CBS,
                                         1.0f, nullptr, nullptr, 0);
    }

    // 6. out = wp @ ao + bp + x
    {
        dim3 grid(HW / 128, C / 128, BATCH);
        gemm_mma<0, 0, 0><<<grid, 256>>>(rwp, aot, out, C,
                                         C, 0, C, CBS, HW, CBS,
                                         1.0f, bp, x, CBS);
    }
}